// round 14
// baseline (speedup 1.0000x reference)
#include <cuda_runtime.h>
#include <cstdint>

#define NB 128
#define NV 128000
#define KTOP 20
#define CHUNKS 8
#define TVEC 4000           // vec4 per tile (16000 elems)
#define ABLK 512
#define CAPG 1024
#define THRESH 3.0f

__device__ unsigned long long g_cand[NB][CAPG];
__device__ unsigned long long g_gkey[NB];
__device__ int   g_cnt[NB];
__device__ int   g_done[NB];
__device__ float g_sums[NB][CHUNKS];

__device__ __forceinline__ float fast_ex2(float x) {
    float r; asm("ex2.approx.ftz.f32 %0, %1;" : "=f"(r) : "f"(x)); return r;
}
__device__ __forceinline__ float fast_lg2(float x) {
    float r; asm("lg2.approx.ftz.f32 %0, %1;" : "=f"(r) : "f"(x)); return r;
}

// Streaming vec4 load pinned in SASS order (asm volatile).
__device__ __forceinline__ float4 ldg_cs4(const float4* p) {
    float4 v;
    asm volatile("ld.global.cs.v4.f32 {%0,%1,%2,%3}, [%4];"
                 : "=f"(v.x), "=f"(v.y), "=f"(v.z), "=f"(v.w) : "l"(p));
    return v;
}

// Monotone pack: larger value wins; on equal value, SMALLER index wins (jax tie rule).
__device__ __forceinline__ unsigned long long packkey(float v, int idx) {
    unsigned fb = __float_as_uint(v);
    fb = (fb & 0x80000000u) ? ~fb : (fb | 0x80000000u);
    return ((unsigned long long)fb << 32) | (unsigned long long)(~(unsigned)idx);
}

// Accurate -ln(u) for u in (0,1): poly(log1p) near 1, MUFU lg2 elsewhere.
__device__ __forceinline__ float neg_log(float u) {
    float d = u - 1.0f;
    float p = fmaf(d, 0.2f, -0.25f);
    p = fmaf(d, p, 0.333333333f);
    p = fmaf(d, p, -0.5f);
    p = fmaf(d, p, 1.0f);
    float lp = -d * p;                        // -log1p(d), good for d in (-0.16, 0]
    float lm = -0.693147181f * fast_lg2(u);
    return (u > 0.84f) ? lp : lm;
}

// Cold path behind an ABI boundary: keeps the scan loop's register allocation
// independent of the combine code (the R6/R7/R8 regression mechanism).
__device__ __noinline__ void combine_row(
    int row, int tid, bool greedy, float inv_t,
    const float* __restrict__ logits, float* __restrict__ out,
    unsigned long long* s_keys, unsigned long long* s_sel,
    unsigned long long* s_win, float* s_lse)
{
    const int cnt = *(volatile int*)&g_cnt[row];
    if (tid == 0) {
        float s = 0.0f;
        #pragma unroll
        for (int c2 = 0; c2 < CHUNKS; c2++) s += g_sums[row][c2];
        *s_lse = 0.693147181f * fast_lg2(s);
    }

    const bool ok = (cnt >= KTOP) && (cnt <= CAPG);
    if (ok) {
        for (int p = tid; p < cnt; p += ABLK) s_keys[p] = g_cand[row][p];
        __syncthreads();
        for (int p = tid; p < cnt; p += ABLK) {
            unsigned long long k = s_keys[p];
            int rank = 0;
            for (int j = 0; j < cnt; j++) rank += (s_keys[j] > k) ? 1 : 0;
            if (rank < KTOP) s_sel[rank] = k;
        }
    } else {
        // robust fallback: 20 rounds of full-row argmax (statistically never)
        unsigned long long bound = 0xFFFFFFFFFFFFFFFFull;
        const float* lrow = logits + (size_t)row * NV;
        for (int r = 0; r < KTOP; r++) {
            __syncthreads();
            if (tid == 0) *s_win = 0ull;
            __syncthreads();
            unsigned long long loc = 0ull;
            for (int p = tid; p < NV; p += ABLK) {
                unsigned long long k = packkey(lrow[p], p);
                if (k < bound && k > loc) loc = k;
            }
            if (loc) atomicMax(s_win, loc);
            __syncthreads();
            bound = *s_win;
            if (tid == 0) s_sel[r] = *s_win;
        }
    }
    __syncthreads();

    if (tid < KTOP) {
        unsigned long long k = s_sel[tid];
        unsigned fb = (unsigned)(k >> 32);
        fb = (fb & 0x80000000u) ? (fb ^ 0x80000000u) : ~fb;
        float val = __uint_as_float(fb);
        int   idx = (int)(~(unsigned)(k & 0xFFFFFFFFull));
        out[NB + row * KTOP + tid]             = val * inv_t - *s_lse;
        out[NB + NB * KTOP + row * KTOP + tid] = (float)idx;
    }
    if (tid == 0) {
        int gi = (int)(~(unsigned)(g_gkey[row] & 0xFFFFFFFFull));
        int i0 = (int)(~(unsigned)(s_sel[0] & 0xFFFFFFFFull));
        out[row] = (float)(greedy ? i0 : gi);
        // reset per-row state for the next graph replay (no other CTA of this row alive)
        g_cnt[row]  = 0;
        g_done[row] = 0;
        g_gkey[row] = 0ull;
    }
}

__global__ __launch_bounds__(ABLK) void sampler_kernel(
    const float* __restrict__ logits,
    const float* __restrict__ temp,
    const float* __restrict__ u,
    float* __restrict__ out)
{
    const int t     = blockIdx.x;
    const int row   = t >> 3;
    const int chunk = t & 7;
    const int tid   = threadIdx.x;

    __shared__ float s_warp[ABLK / 32];
    __shared__ unsigned long long s_best;
    __shared__ unsigned long long s_keys[CAPG];
    __shared__ unsigned long long s_sel[KTOP];
    __shared__ unsigned long long s_win;
    __shared__ float s_lse;
    __shared__ int   s_last;
    if (tid == 0) s_best = 0ull;
    __syncthreads();

    const float tv    = temp[row];
    const bool greedy = (tv < 1e-5f);
    const float tt    = greedy ? 1.0f : tv;
    const float inv_t = 1.0f / tt;
    const float c     = inv_t * 1.44269504088896f;

    const float4* __restrict__ lg4 = (const float4*)(logits + (size_t)row * NV) + chunk * TVEC;
    const float4* __restrict__ u4  = (const float4*)(u      + (size_t)row * NV) + chunk * TVEC;
    const int ebase = 4 * chunk * TVEC;

    float acc0 = 0.0f, acc1 = 0.0f;
    float best_e  = 0.0f;
    float best_lq = 1.0f;
    int   best_gi = 0;
    float invK    = 1e30f;

    #define RARE(lv, uv, ee, gidx)                                                  \
    {                                                                               \
        if ((lv) > THRESH) {                                                        \
            int p = atomicAdd(&g_cnt[row], 1);                                      \
            if (p < CAPG) g_cand[row][p] = packkey((lv), (gidx));                   \
        }                                                                           \
        if (fmaf((ee), invK, (uv)) > 0.999f) {                                      \
            float lq = neg_log(uv);                                                 \
            if ((ee) * best_lq > best_e * lq) {                                     \
                best_e = (ee); best_lq = lq; best_gi = (gidx);                      \
                invK = 1.01f * (lq / (ee));                                         \
            }                                                                       \
        }                                                                           \
    }
    #define ELEM(lv, uv, ee, gidx)                                                  \
    {                                                                               \
        bool hot = ((lv) > THRESH) | (fmaf((ee), invK, (uv)) > 0.999f);             \
        if (hot) RARE(lv, uv, ee, gidx)                                             \
    }

    // Proven R5 scan: 2-deep batches, warp-uniform guards (all boundaries %32==0).
    for (int i = tid; i < TVEC; i += 2 * ABLK) {
        bool hasB = (i + ABLK) < TVEC;
        float4 L0, U0, L1, U1;
        if (hasB) {
            L0 = ldg_cs4(lg4 + i);
            U0 = ldg_cs4(u4  + i);
            L1 = ldg_cs4(lg4 + i + ABLK);
            U1 = ldg_cs4(u4  + i + ABLK);
        } else {
            L0 = ldg_cs4(lg4 + i);
            U0 = ldg_cs4(u4  + i);
        }

        float e0 = fast_ex2(L0.x * c), e1 = fast_ex2(L0.y * c);
        float e2 = fast_ex2(L0.z * c), e3 = fast_ex2(L0.w * c);
        acc0 += (e0 + e1) + (e2 + e3);
        int g0 = ebase + 4 * i;
        ELEM(L0.x, U0.x, e0, g0 + 0) ELEM(L0.y, U0.y, e1, g0 + 1)
        ELEM(L0.z, U0.z, e2, g0 + 2) ELEM(L0.w, U0.w, e3, g0 + 3)

        if (hasB) {
            float e4 = fast_ex2(L1.x * c), e5 = fast_ex2(L1.y * c);
            float e6 = fast_ex2(L1.z * c), e7 = fast_ex2(L1.w * c);
            acc1 += (e4 + e5) + (e6 + e7);
            int g1 = ebase + 4 * (i + ABLK);
            ELEM(L1.x, U1.x, e4, g1 + 0) ELEM(L1.y, U1.y, e5, g1 + 1)
            ELEM(L1.z, U1.z, e6, g1 + 2) ELEM(L1.w, U1.w, e7, g1 + 3)
        }
    }
    #undef ELEM
    #undef RARE

    // ---- per-tile reductions ----
    float sumexp = acc0 + acc1;
    #pragma unroll
    for (int o = 16; o; o >>= 1) sumexp += __shfl_down_sync(0xFFFFFFFFu, sumexp, o);
    if ((tid & 31) == 0) s_warp[tid >> 5] = sumexp;
    atomicMax(&s_best, packkey(best_e / best_lq, best_gi));
    __syncthreads();

    if (tid == 0) {
        float s = 0.0f;
        #pragma unroll
        for (int w = 0; w < ABLK / 32; w++) s += s_warp[w];
        g_sums[row][chunk] = s;                       // fixed slot -> deterministic re-sum
        atomicMax(&g_gkey[row], s_best);              // commutative -> deterministic
    }

    // ---- last-CTA-per-row handoff ----
    __threadfence();
    __syncthreads();
    if (tid == 0) s_last = (atomicAdd(&g_done[row], 1) == CHUNKS - 1) ? 1 : 0;
    __syncthreads();
    if (!s_last) return;

    combine_row(row, tid, greedy, inv_t, logits, out, s_keys, s_sel, &s_win, &s_lse);
}

extern "C" void kernel_launch(void* const* d_in, const int* in_sizes, int n_in,
                              void* d_out, int out_size) {
    const float* logits = (const float*)d_in[0];
    const float* temp   = (const float*)d_in[1];
    const float* u      = (const float*)d_in[2];
    (void)in_sizes; (void)n_in; (void)out_size;
    sampler_kernel<<<NB * CHUNKS, ABLK>>>(logits, temp, u, (float*)d_out);
}

// round 15
// speedup vs baseline: 1.0097x; 1.0097x over previous
#include <cuda_runtime.h>
#include <cstdint>

#define NB 128
#define NV 128000
#define KTOP 20
#define CHUNKS 8
#define TVEC 4000           // vec4 per tile (16000 elems)
#define ABLK 512
#define CBLK 256
#define CAPG 1024
#define THRESH 3.0f

__device__ unsigned long long g_cand[NB][CAPG];
__device__ unsigned long long g_gkey[NB];
__device__ int   g_cnt[NB];
__device__ float g_sums[NB][CHUNKS];

__device__ __forceinline__ float fast_ex2(float x) {
    float r; asm("ex2.approx.ftz.f32 %0, %1;" : "=f"(r) : "f"(x)); return r;
}
__device__ __forceinline__ float fast_lg2(float x) {
    float r; asm("lg2.approx.ftz.f32 %0, %1;" : "=f"(r) : "f"(x)); return r;
}

// Streaming vec4 load pinned in SASS order (asm volatile).
__device__ __forceinline__ float4 ldg_cs4(const float4* p) {
    float4 v;
    asm volatile("ld.global.cs.v4.f32 {%0,%1,%2,%3}, [%4];"
                 : "=f"(v.x), "=f"(v.y), "=f"(v.z), "=f"(v.w) : "l"(p));
    return v;
}

// Monotone pack: larger value wins; on equal value, SMALLER index wins (jax tie rule).
__device__ __forceinline__ unsigned long long packkey(float v, int idx) {
    unsigned fb = __float_as_uint(v);
    fb = (fb & 0x80000000u) ? ~fb : (fb | 0x80000000u);
    return ((unsigned long long)fb << 32) | (unsigned long long)(~(unsigned)idx);
}

// Accurate -ln(u) for u in (0,1): poly(log1p) near 1, MUFU lg2 elsewhere.
__device__ __forceinline__ float neg_log(float u) {
    float d = u - 1.0f;
    float p = fmaf(d, 0.2f, -0.25f);
    p = fmaf(d, p, 0.333333333f);
    p = fmaf(d, p, -0.5f);
    p = fmaf(d, p, 1.0f);
    float lp = -d * p;                        // -log1p(d), good for d in (-0.16, 0]
    float lm = -0.693147181f * fast_lg2(u);
    return (u > 0.84f) ? lp : lm;
}

// ---------------- Kernel A: per-tile scan (no combine code at all) ----------------
__global__ __launch_bounds__(ABLK) void scan_kernel(
    const float* __restrict__ logits,
    const float* __restrict__ temp,
    const float* __restrict__ u)
{
    const int t     = blockIdx.x;
    const int row   = t >> 3;
    const int chunk = t & 7;
    const int tid   = threadIdx.x;

    __shared__ float s_warp[ABLK / 32];
    __shared__ unsigned long long s_best;
    if (tid == 0) s_best = 0ull;
    __syncthreads();

    const float tv = temp[row];
    const float tt = (tv < 1e-5f) ? 1.0f : tv;
    const float c  = (1.0f / tt) * 1.44269504088896f;

    const float4* __restrict__ lg4 = (const float4*)(logits + (size_t)row * NV) + chunk * TVEC;
    const float4* __restrict__ u4  = (const float4*)(u      + (size_t)row * NV) + chunk * TVEC;
    const int ebase = 4 * chunk * TVEC;

    float acc0 = 0.0f, acc1 = 0.0f;
    float best_e  = 0.0f;
    float best_lq = 1.0f;
    int   best_gi = 0;
    float invK    = 1e30f;

    #define RARE(lv, uv, ee, gidx)                                                  \
    {                                                                               \
        if ((lv) > THRESH) {                                                        \
            int p = atomicAdd(&g_cnt[row], 1);                                      \
            if (p < CAPG) g_cand[row][p] = packkey((lv), (gidx));                   \
        }                                                                           \
        if (fmaf((ee), invK, (uv)) > 0.999f) {                                      \
            float lq = neg_log(uv);                                                 \
            if ((ee) * best_lq > best_e * lq) {                                     \
                best_e = (ee); best_lq = lq; best_gi = (gidx);                      \
                invK = 1.01f * (lq / (ee));                                         \
            }                                                                       \
        }                                                                           \
    }
    #define ELEM(lv, uv, ee, gidx)                                                  \
    {                                                                               \
        bool hot = ((lv) > THRESH) | (fmaf((ee), invK, (uv)) > 0.999f);             \
        if (hot) RARE(lv, uv, ee, gidx)                                             \
    }
    #define PROC(L, U, goff)                                                        \
    {                                                                               \
        float e0 = fast_ex2(L.x * c), e1 = fast_ex2(L.y * c);                       \
        float e2 = fast_ex2(L.z * c), e3 = fast_ex2(L.w * c);                       \
        acc0 += (e0 + e1); acc1 += (e2 + e3);                                       \
        ELEM(L.x, U.x, e0, (goff) + 0) ELEM(L.y, U.y, e1, (goff) + 1)               \
        ELEM(L.z, U.z, e2, (goff) + 2) ELEM(L.w, U.w, e3, (goff) + 3)               \
    }

    // R9-proven 3-deep pinned batches. TVEC=4000: main loop covers 3×512×2=3072,
    // remainder loop covers the rest; all guards warp-uniform (bounds %32==0).
    int i = tid;
    for (; i + 2 * ABLK < TVEC; i += 3 * ABLK) {
        float4 L0 = ldg_cs4(lg4 + i);
        float4 U0 = ldg_cs4(u4  + i);
        float4 L1 = ldg_cs4(lg4 + i + ABLK);
        float4 U1 = ldg_cs4(u4  + i + ABLK);
        float4 L2 = ldg_cs4(lg4 + i + 2 * ABLK);
        float4 U2 = ldg_cs4(u4  + i + 2 * ABLK);
        PROC(L0, U0, ebase + 4 * i)
        PROC(L1, U1, ebase + 4 * (i + ABLK))
        PROC(L2, U2, ebase + 4 * (i + 2 * ABLK))
    }
    for (; i < TVEC; i += ABLK) {
        float4 L0 = ldg_cs4(lg4 + i);
        float4 U0 = ldg_cs4(u4  + i);
        PROC(L0, U0, ebase + 4 * i)
    }
    #undef PROC
    #undef ELEM
    #undef RARE

    float sumexp = acc0 + acc1;
    #pragma unroll
    for (int o = 16; o; o >>= 1) sumexp += __shfl_down_sync(0xFFFFFFFFu, sumexp, o);
    if ((tid & 31) == 0) s_warp[tid >> 5] = sumexp;
    atomicMax(&s_best, packkey(best_e / best_lq, best_gi));
    __syncthreads();

    if (tid == 0) {
        float s = 0.0f;
        #pragma unroll
        for (int w = 0; w < ABLK / 32; w++) s += s_warp[w];
        g_sums[row][chunk] = s;                       // fixed slot -> deterministic re-sum
        atomicMax(&g_gkey[row], s_best);              // commutative -> deterministic
    }
}

// ---------------- Kernel B: per-row combine (slim) ----------------
__global__ __launch_bounds__(CBLK) void combine_kernel(
    const float* __restrict__ logits,
    const float* __restrict__ temp,
    float* __restrict__ out)
{
    const int row = blockIdx.x;
    const int tid = threadIdx.x;

    __shared__ unsigned long long s_keys[CAPG + 4];
    __shared__ unsigned long long s_sel[KTOP];
    __shared__ unsigned long long s_win;
    __shared__ float s_lse;

    const int cnt = g_cnt[row];
    const float tv     = temp[row];
    const bool  greedy = (tv < 1e-5f);
    const float inv_t  = 1.0f / (greedy ? 1.0f : tv);

    if (tid == 0) {
        float s = 0.0f;
        #pragma unroll
        for (int c2 = 0; c2 < CHUNKS; c2++) s += g_sums[row][c2];
        s_lse = 0.693147181f * fast_lg2(s);
    }

    const bool ok = (cnt >= KTOP) && (cnt <= CAPG);
    if (ok) {
        const int cnt4 = (cnt + 3) & ~3;              // pad to multiple of 4
        for (int p = tid; p < cnt4; p += CBLK)
            s_keys[p] = (p < cnt) ? g_cand[row][p] : 0ull;   // 0 = smallest key
        __syncthreads();
        for (int p = tid; p < cnt; p += CBLK) {
            unsigned long long k = s_keys[p];
            int rank = 0;
            for (int j = 0; j < cnt4; j += 4) {       // unrolled x4, padded tail safe
                rank += (s_keys[j + 0] > k) ? 1 : 0;
                rank += (s_keys[j + 1] > k) ? 1 : 0;
                rank += (s_keys[j + 2] > k) ? 1 : 0;
                rank += (s_keys[j + 3] > k) ? 1 : 0;
            }
            if (rank < KTOP) s_sel[rank] = k;
        }
    } else {
        // robust fallback: 20 rounds of full-row argmax (statistically never)
        unsigned long long bound = 0xFFFFFFFFFFFFFFFFull;
        const float* lrow = logits + (size_t)row * NV;
        for (int r = 0; r < KTOP; r++) {
            __syncthreads();
            if (tid == 0) s_win = 0ull;
            __syncthreads();
            unsigned long long loc = 0ull;
            for (int p = tid; p < NV; p += CBLK) {
                unsigned long long k = packkey(lrow[p], p);
                if (k < bound && k > loc) loc = k;
            }
            if (loc) atomicMax(&s_win, loc);
            __syncthreads();
            bound = s_win;
            if (tid == 0) s_sel[r] = s_win;
        }
    }
    __syncthreads();

    if (tid < KTOP) {
        unsigned long long k = s_sel[tid];
        unsigned fb = (unsigned)(k >> 32);
        fb = (fb & 0x80000000u) ? (fb ^ 0x80000000u) : ~fb;
        float val = __uint_as_float(fb);
        int   idx = (int)(~(unsigned)(k & 0xFFFFFFFFull));
        out[NB + row * KTOP + tid]             = val * inv_t - s_lse;
        out[NB + NB * KTOP + row * KTOP + tid] = (float)idx;
    }
    if (tid == 0) {
        int gi = (int)(~(unsigned)(g_gkey[row] & 0xFFFFFFFFull));
        int i0 = (int)(~(unsigned)(s_sel[0] & 0xFFFFFFFFull));
        out[row] = (float)(greedy ? i0 : gi);
        // reset per-row state for next graph replay
        g_cnt[row]  = 0;
        g_gkey[row] = 0ull;
    }
}

extern "C" void kernel_launch(void* const* d_in, const int* in_sizes, int n_in,
                              void* d_out, int out_size) {
    const float* logits = (const float*)d_in[0];
    const float* temp   = (const float*)d_in[1];
    const float* u      = (const float*)d_in[2];
    (void)in_sizes; (void)n_in; (void)out_size;
    scan_kernel<<<NB * CHUNKS, ABLK>>>(logits, temp, u);
    combine_kernel<<<NB, CBLK>>>(logits, temp, (float*)d_out);
}

// round 16
// speedup vs baseline: 1.5014x; 1.4870x over previous
#include <cuda_runtime.h>
#include <cstdint>

#define NB 128
#define NV 128000
#define KTOP 20
#define NTHREADS 1024
#define CAP 4096
#define THRESH 3.0f

__device__ __forceinline__ float fast_ex2(float x) {
    float r; asm("ex2.approx.ftz.f32 %0, %1;" : "=f"(r) : "f"(x)); return r;
}
__device__ __forceinline__ float fast_lg2(float x) {
    float r; asm("lg2.approx.ftz.f32 %0, %1;" : "=f"(r) : "f"(x)); return r;
}

// Streaming vec4 load pinned in SASS order (asm volatile).
__device__ __forceinline__ float4 ldg_cs4(const float4* p) {
    float4 v;
    asm volatile("ld.global.cs.v4.f32 {%0,%1,%2,%3}, [%4];"
                 : "=f"(v.x), "=f"(v.y), "=f"(v.z), "=f"(v.w) : "l"(p));
    return v;
}

// Monotone pack: larger value wins; on equal value, SMALLER index wins (jax tie rule).
__device__ __forceinline__ unsigned long long packkey(float v, int idx) {
    unsigned fb = __float_as_uint(v);
    fb = (fb & 0x80000000u) ? ~fb : (fb | 0x80000000u);
    return ((unsigned long long)fb << 32) | (unsigned long long)(~(unsigned)idx);
}

// Accurate -ln(u) for u in (0,1): poly(log1p) near 1, MUFU lg2 elsewhere.
__device__ __forceinline__ float neg_log(float u) {
    float d = u - 1.0f;
    float p = fmaf(d, 0.2f, -0.25f);
    p = fmaf(d, p, 0.333333333f);
    p = fmaf(d, p, -0.5f);
    p = fmaf(d, p, 1.0f);
    float lp = -d * p;                        // -log1p(d), good for d in (-0.16, 0]
    float lm = -0.693147181f * fast_lg2(u);
    return (u > 0.84f) ? lp : lm;
}

__global__ __launch_bounds__(NTHREADS) void sampler_kernel(
    const float* __restrict__ logits,
    const float* __restrict__ temp,
    const float* __restrict__ u,
    float* __restrict__ out)
{
    const int b   = blockIdx.x;
    const int tid = threadIdx.x;

    __shared__ float s_val[CAP];
    __shared__ int   s_idx[CAP];
    __shared__ int   s_cnt;
    __shared__ float s_warp[NTHREADS / 32];
    __shared__ unsigned long long s_gkey;
    __shared__ unsigned long long s_win;
    __shared__ float s_lse;
    __shared__ float s_selval[KTOP];
    __shared__ int   s_selidx[KTOP];

    if (tid == 0) { s_cnt = 0; s_gkey = 0ull; }
    __syncthreads();

    const float t      = temp[b];
    const bool  greedy = (t < 1e-5f);
    const float tt     = greedy ? 1.0f : t;
    const float inv_t  = 1.0f / tt;
    const float c      = inv_t * 1.44269504088896f;

    const float4* __restrict__ lg4 = (const float4*)(logits + (size_t)b * NV);
    const float4* __restrict__ u4  = (const float4*)(u      + (size_t)b * NV);

    float acc0 = 0.0f, acc1 = 0.0f;
    float best_e  = 0.0f;
    float best_lq = 1.0f;
    int   best_gi = 0;
    float invK    = 1e30f;

    const int nvec = NV / 4;   // 32000

    if (greedy) {
        // ---- greedy rows (every 4th): u is never consumed by the reference.
        // Skip the u stream entirely (12.5% of total kernel DRAM traffic) and
        // the Gumbel filter; only sumexp + top-k candidate collection remain.
        #define GELEM(lv, gidx)                                                     \
        {                                                                           \
            if ((lv) > THRESH) {                                                    \
                int p = atomicAdd(&s_cnt, 1);                                       \
                if (p < CAP) { s_val[p] = (lv); s_idx[p] = (gidx); }                \
            }                                                                       \
        }
        #define GPROC(L, goff)                                                      \
        {                                                                           \
            float e0 = fast_ex2(L.x * c), e1 = fast_ex2(L.y * c);                   \
            float e2 = fast_ex2(L.z * c), e3 = fast_ex2(L.w * c);                   \
            acc0 += (e0 + e1); acc1 += (e2 + e3);                                   \
            GELEM(L.x, (goff) + 0) GELEM(L.y, (goff) + 1)                           \
            GELEM(L.z, (goff) + 2) GELEM(L.w, (goff) + 3)                           \
        }
        int i = tid;
        for (; i + 2 * NTHREADS < nvec; i += 3 * NTHREADS) {
            float4 L0 = ldg_cs4(lg4 + i);
            float4 L1 = ldg_cs4(lg4 + i + NTHREADS);
            float4 L2 = ldg_cs4(lg4 + i + 2 * NTHREADS);
            GPROC(L0, 4 * i)
            GPROC(L1, 4 * (i + NTHREADS))
            GPROC(L2, 4 * (i + 2 * NTHREADS))
        }
        for (; i < nvec; i += NTHREADS) {
            float4 L0 = ldg_cs4(lg4 + i);
            GPROC(L0, 4 * i)
        }
        #undef GPROC
        #undef GELEM
    } else {
        // ---- non-greedy rows: exact R9 loop ----
        #define RARE(lv, uv, ee, gidx)                                              \
        {                                                                           \
            if ((lv) > THRESH) {                                                    \
                int p = atomicAdd(&s_cnt, 1);                                       \
                if (p < CAP) { s_val[p] = (lv); s_idx[p] = (gidx); }                \
            }                                                                       \
            if (fmaf((ee), invK, (uv)) > 0.999f) {                                  \
                float lq = neg_log(uv);                                             \
                if ((ee) * best_lq > best_e * lq) {                                 \
                    best_e = (ee); best_lq = lq; best_gi = (gidx);                  \
                    invK = 1.01f * (lq / (ee));                                     \
                }                                                                   \
            }                                                                       \
        }
        #define ELEM(lv, uv, ee, gidx)                                              \
        {                                                                           \
            bool hot = ((lv) > THRESH) | (fmaf((ee), invK, (uv)) > 0.999f);         \
            if (hot) RARE(lv, uv, ee, gidx)                                         \
        }
        #define PROC(L, U, goff)                                                    \
        {                                                                           \
            float e0 = fast_ex2(L.x * c), e1 = fast_ex2(L.y * c);                   \
            float e2 = fast_ex2(L.z * c), e3 = fast_ex2(L.w * c);                   \
            acc0 += (e0 + e1); acc1 += (e2 + e3);                                   \
            ELEM(L.x, U.x, e0, (goff) + 0) ELEM(L.y, U.y, e1, (goff) + 1)           \
            ELEM(L.z, U.z, e2, (goff) + 2) ELEM(L.w, U.w, e3, (goff) + 3)           \
        }
        int i = tid;
        for (; i + 2 * NTHREADS < nvec; i += 3 * NTHREADS) {
            float4 L0 = ldg_cs4(lg4 + i);
            float4 U0 = ldg_cs4(u4  + i);
            float4 L1 = ldg_cs4(lg4 + i + NTHREADS);
            float4 U1 = ldg_cs4(u4  + i + NTHREADS);
            float4 L2 = ldg_cs4(lg4 + i + 2 * NTHREADS);
            float4 U2 = ldg_cs4(u4  + i + 2 * NTHREADS);
            PROC(L0, U0, 4 * i)
            PROC(L1, U1, 4 * (i + NTHREADS))
            PROC(L2, U2, 4 * (i + 2 * NTHREADS))
        }
        for (; i < nvec; i += NTHREADS) {
            float4 L0 = ldg_cs4(lg4 + i);
            float4 U0 = ldg_cs4(u4  + i);
            PROC(L0, U0, 4 * i)
        }
        #undef PROC
        #undef ELEM
        #undef RARE
    }

    // ---- sumexp reduction ----
    float sumexp = acc0 + acc1;
    #pragma unroll
    for (int o = 16; o; o >>= 1) sumexp += __shfl_down_sync(0xFFFFFFFFu, sumexp, o);
    if ((tid & 31) == 0) s_warp[tid >> 5] = sumexp;

    // ---- Gumbel winner across threads (key 0 for greedy rows; never read) ----
    atomicMax(&s_gkey, packkey(best_e / best_lq, best_gi));
    __syncthreads();

    if (tid == 0) {
        float s = 0.0f;
        #pragma unroll
        for (int w = 0; w < NTHREADS / 32; w++) s += s_warp[w];
        s_lse = 0.693147181f * fast_lg2(s);
    }

    // ---- top-K: single-pass rank selection over shared candidates ----
    const int cnt = s_cnt;
    const bool okc = (cnt >= KTOP) && (cnt <= CAP);
    if (okc) {
        for (int p = tid; p < cnt; p += NTHREADS) {
            float v = s_val[p]; int ix = s_idx[p];
            unsigned long long my = packkey(v, ix);
            int rank = 0;
            for (int j = 0; j < cnt; j++)
                rank += (packkey(s_val[j], s_idx[j]) > my) ? 1 : 0;
            if (rank < KTOP) { s_selval[rank] = v; s_selidx[rank] = ix; }
        }
    } else {
        // robust fallback: 20 rounds of global argmax with exclusion (statistically never)
        unsigned long long bound = 0xFFFFFFFFFFFFFFFFull;
        const float* lrow = logits + (size_t)b * NV;
        for (int r = 0; r < KTOP; r++) {
            __syncthreads();
            if (tid == 0) s_win = 0ull;
            __syncthreads();
            unsigned long long loc = 0ull;
            for (int p = tid; p < NV; p += NTHREADS) {
                unsigned long long k = packkey(lrow[p], p);
                if (k < bound && k > loc) loc = k;
            }
            if (loc) atomicMax(&s_win, loc);
            __syncthreads();
            unsigned long long w = s_win;
            bound = w;
            if (tid == 0) {
                unsigned fb = (unsigned)(w >> 32);
                fb = (fb & 0x80000000u) ? (fb ^ 0x80000000u) : ~fb;
                s_selval[r] = __uint_as_float(fb);
                s_selidx[r] = (int)(~(unsigned)(w & 0xFFFFFFFFull));
            }
        }
    }
    __syncthreads();

    // ---- outputs: [sampled(NB) | topk_logprobs(NB*K) | topk_indices(NB*K)] ----
    if (tid < KTOP) {
        float lp = s_selval[tid] * inv_t - s_lse;
        out[NB + b * KTOP + tid]             = lp;
        out[NB + NB * KTOP + b * KTOP + tid] = (float)s_selidx[tid];
    }
    if (tid == 0) {
        int gi = (int)(~(unsigned)(s_gkey & 0xFFFFFFFFull));
        out[b] = (float)(greedy ? s_selidx[0] : gi);
    }
}

extern "C" void kernel_launch(void* const* d_in, const int* in_sizes, int n_in,
                              void* d_out, int out_size) {
    const float* logits = (const float*)d_in[0];
    const float* temp   = (const float*)d_in[1];
    const float* u      = (const float*)d_in[2];
    (void)in_sizes; (void)n_in; (void)out_size;
    sampler_kernel<<<NB, NTHREADS>>>(logits, temp, u, (float*)d_out);
}